// round 13
// baseline (speedup 1.0000x reference)
#include <cuda_runtime.h>
#include <cuda_bf16.h>
#include <cuda_fp16.h>
#include <cstdint>

// GATv2 with algebraic reductions:
//   attn[e,h] = exp(ql[src]) / sum_{s in N(dst)} exp(ql[s])   (kl cancels -> Wk/bk unused)
//   out[d] = relu( sum_{s in N(d)} P[s] / sum_{s in N(d)} w[s] ),
//   P = q * exp(ql) (fp16), w = exp(ql) (fp32), node-level (GEMM epilogue).
// 3 kernels: [build_w + hist] -> [scan(blk0) | gemm | scatter(spin on flag)] -> [gather].
// Invariants across launches (graph replay): g_cnt all-zero, g_flag==0, g_done==0.

#define MAXN 50000
#define MAXE 600000

__device__ __half         g_P   [MAXN * 128];   // q * exp(ql), fp16
__device__ float          g_w   [MAXN * 8];     // exp(ql)
__device__ __nv_bfloat16  g_Bhi [136 * 128];    // Wf^T hi  [c][k]
__device__ __nv_bfloat16  g_Blo [136 * 128];    // Wf^T lo
__device__ float          g_bf  [136];
__device__ int            g_cnt [MAXN + 4];     // ALWAYS zero between launches
__device__ int            g_roff[MAXN + 4];
__device__ int            g_cur [MAXN + 4];
__device__ int            g_csr [MAXE];
__device__ int            g_flag = 0;           // scan-done flag
__device__ int            g_done = 0;           // scatter completion counter

// ---------------------------------------------------------------------------
// K0: fused weight build (idx < 17544) + dst-degree histogram (4 edges/thread).
// ---------------------------------------------------------------------------
__global__ void build_hist_kernel(const float* __restrict__ Wq, const float* __restrict__ bq,
                                  const float* __restrict__ aw,
                                  const int* __restrict__ dst, int E)
{
    int idx = blockIdx.x * blockDim.x + threadIdx.x;
    if (idx < 128 * 136) {
        int r = idx / 136, c = idx % 136;   // r = k index, c = output col
        float v;
        if (c < 128) {
            v = Wq[r * 128 + c];
        } else {
            int h = c - 128;
            float s = 0.f;
#pragma unroll
            for (int d = 0; d < 16; d++) s += Wq[r * 128 + h * 16 + d] * aw[d * 8 + h];
            v = s;
        }
        __nv_bfloat16 hi = __float2bfloat16(v);
        __nv_bfloat16 lo = __float2bfloat16(v - __bfloat162float(hi));
        g_Bhi[c * 128 + r] = hi;
        g_Blo[c * 128 + r] = lo;
    } else if (idx < 128 * 136 + 136) {
        int c = idx - 128 * 136;
        float v;
        if (c < 128) {
            v = bq[c];
        } else {
            int h = c - 128;
            float s = 0.f;
#pragma unroll
            for (int d = 0; d < 16; d++) s += bq[h * 16 + d] * aw[d * 8 + h];
            v = s;
        }
        g_bf[c] = v;
    }
    // histogram: 4 edges/thread
    int T = gridDim.x * blockDim.x;
    int e0 = idx, e1 = idx + T, e2 = idx + 2 * T, e3 = idx + 3 * T;
    int d0 = (e0 < E) ? dst[e0] : -1;
    int d1 = (e1 < E) ? dst[e1] : -1;
    int d2 = (e2 < E) ? dst[e2] : -1;
    int d3 = (e3 < E) ? dst[e3] : -1;
    if (d0 >= 0) atomicAdd(&g_cnt[d0], 1);
    if (d1 >= 0) atomicAdd(&g_cnt[d1], 1);
    if (d2 >= 0) atomicAdd(&g_cnt[d2], 1);
    if (d3 >= 0) atomicAdd(&g_cnt[d3], 1);
}

// ---------------------------------------------------------------------------
// K1: fused [scan | gemm | scatter] by blockIdx.
//   block 0            : vectorized exclusive scan (256 thr) -> roff/cur,
//                        re-zero cnt, then release g_flag.
//   blocks 1..gemmB    : mma.sync bf16 GEMM (128 rows x 136 cols).
//   blocks gemmB+1 ... : spin on g_flag, then CSR scatter (4 edges/thread).
//                        Last scatter block resets g_flag/g_done (replay-safe).
// ---------------------------------------------------------------------------
#define B_STRIDE 272
#define SMB_HI   0
#define SMB_LO   (136 * B_STRIDE)
#define SMB_TOT  (2 * 136 * B_STRIDE)   // 73984 bytes

__device__ __forceinline__ void mma_bf16(float* c, const uint32_t* a,
                                         uint32_t b0, uint32_t b1) {
    asm volatile(
        "mma.sync.aligned.m16n8k16.row.col.f32.bf16.bf16.f32 "
        "{%0,%1,%2,%3}, {%4,%5,%6,%7}, {%8,%9}, {%0,%1,%2,%3};"
        : "+f"(c[0]), "+f"(c[1]), "+f"(c[2]), "+f"(c[3])
        : "r"(a[0]), "r"(a[1]), "r"(a[2]), "r"(a[3]), "r"(b0), "r"(b1));
}

__device__ __forceinline__ void cvt2(float2 f, uint32_t& hi, uint32_t& lo) {
    __nv_bfloat16 h0 = __float2bfloat16(f.x);
    __nv_bfloat16 h1 = __float2bfloat16(f.y);
    __nv_bfloat16 l0 = __float2bfloat16(f.x - __bfloat162float(h0));
    __nv_bfloat16 l1 = __float2bfloat16(f.y - __bfloat162float(h1));
    __nv_bfloat162 H(h0, h1), L(l0, l1);
    hi = *(uint32_t*)&H;
    lo = *(uint32_t*)&L;
}

__global__ void __launch_bounds__(256) fused_mid_kernel(
    const float* __restrict__ x, const int* __restrict__ src,
    const int* __restrict__ dst, int n, int E, int gemmBlocks, int scatBlocks)
{
    extern __shared__ char smem[];
    int tid = threadIdx.x;
    int bid = blockIdx.x;

    if (bid == 0) {
        // ---------------- scan part (256 threads) ----------------
        __shared__ int sh[256];
        int per = ((n + 255) / 256 + 3) & ~3;
        int beg = tid * per; if (beg > n) beg = n;
        int end = beg + per; if (end > n) end = n;

        int s = 0;
        int i = beg;
        for (; i + 4 <= end; i += 4) {
            int4 v = *(const int4*)&g_cnt[i];
            s += v.x + v.y + v.z + v.w;
        }
        for (; i < end; i++) s += g_cnt[i];
        sh[tid] = s;
        __syncthreads();
#pragma unroll
        for (int off = 1; off < 256; off <<= 1) {
            int v = (tid >= off) ? sh[tid - off] : 0;
            __syncthreads();
            sh[tid] += v;
            __syncthreads();
        }
        int run = (tid > 0) ? sh[tid - 1] : 0;
        const int4 z4 = make_int4(0, 0, 0, 0);
        i = beg;
        for (; i + 4 <= end; i += 4) {
            int4 v = *(const int4*)&g_cnt[i];
            int4 p;
            p.x = run;
            p.y = p.x + v.x;
            p.z = p.y + v.y;
            p.w = p.z + v.z;
            run = p.w + v.w;
            *(int4*)&g_roff[i] = p;
            *(int4*)&g_cur[i]  = p;
            *(int4*)&g_cnt[i]  = z4;       // restore invariant
        }
        for (; i < end; i++) {
            g_roff[i] = run;
            g_cur[i]  = run;
            run += g_cnt[i];
            g_cnt[i] = 0;
        }
        if (tid == 255) g_roff[n] = sh[255];
        __syncthreads();
        __threadfence();
        if (tid == 0) atomicExch(&g_flag, 1);   // release
        return;
    }

    if (bid > gemmBlocks) {
        // ---------------- scatter part (spin until scan done) ----------------
        if (tid == 0) {
            while (atomicAdd(&g_flag, 0) == 0) __nanosleep(128);
        }
        __syncthreads();
        __threadfence();                         // acquire

        int b = bid - gemmBlocks - 1;
        int t = b * 256 + tid;
        int T = scatBlocks * 256;
#pragma unroll
        for (int j = 0; j < 4; j++) {
            int e = t + j * T;
            if (e < E) {
                int pos = atomicAdd(&g_cur[dst[e]], 1);
                g_csr[pos] = src[e];
            }
        }
        __syncthreads();
        if (tid == 0) {
            int d = atomicAdd(&g_done, 1);
            if (d == scatBlocks - 1) {           // last scatter block: reset state
                atomicExch(&g_flag, 0);
                atomicExch(&g_done, 0);
            }
        }
        return;
    }

    // ---------------- gemm part ----------------
    char* bhi = smem + SMB_HI;
    char* blo = smem + SMB_LO;

    for (int idx = tid; idx < 136 * 16; idx += 256) {
        int row = idx >> 4, j = idx & 15;
        *(uint4*)(bhi + row * B_STRIDE + j * 16) = *(const uint4*)&g_Bhi[row * 128 + j * 8];
        *(uint4*)(blo + row * B_STRIDE + j * 16) = *(const uint4*)&g_Blo[row * 128 + j * 8];
    }
    __syncthreads();

    int w    = tid >> 5;
    int lane = tid & 31;
    int g    = lane >> 2;
    int t    = lane & 3;
    int rb   = (bid - 1) * 128 + w * 16;
    int r0   = rb + g;
    int r1   = r0 + 8;
    int rc0  = (r0 < n) ? r0 : (n - 1);
    int rc1  = (r1 < n) ? r1 : (n - 1);
    const float* xr0 = &x[(size_t)rc0 * 128];
    const float* xr1 = &x[(size_t)rc1 * 128];

    float C[17][4];
#pragma unroll
    for (int j = 0; j < 17; j++)
#pragma unroll
        for (int q = 0; q < 4; q++) C[j][q] = 0.f;

    for (int k0 = 0; k0 < 128; k0 += 16) {
        float2 f00 = *(const float2*)&xr0[k0 + 2 * t];
        float2 f10 = *(const float2*)&xr1[k0 + 2 * t];
        float2 f01 = *(const float2*)&xr0[k0 + 2 * t + 8];
        float2 f11 = *(const float2*)&xr1[k0 + 2 * t + 8];
        uint32_t ah[4], al[4];
        cvt2(f00, ah[0], al[0]);
        cvt2(f10, ah[1], al[1]);
        cvt2(f01, ah[2], al[2]);
        cvt2(f11, ah[3], al[3]);

        const char* bh = bhi + k0 * 2 + t * 4;
        const char* bl = blo + k0 * 2 + t * 4;
#pragma unroll
        for (int j = 0; j < 17; j++) {
            int brow = (j * 8 + g) * B_STRIDE;
            uint32_t bh0 = *(const uint32_t*)(bh + brow);
            uint32_t bh1 = *(const uint32_t*)(bh + brow + 16);
            uint32_t bl0 = *(const uint32_t*)(bl + brow);
            uint32_t bl1 = *(const uint32_t*)(bl + brow + 16);
            mma_bf16(C[j], ah, bh0, bh1);
            mma_bf16(C[j], al, bh0, bh1);
            mma_bf16(C[j], ah, bl0, bl1);
        }
    }

    // epilogue: e = exp(ql + bias); quad-broadcast; write P (fp16) and w (fp32)
    bool v0 = (r0 < n), v1 = (r1 < n);
    float bql0 = g_bf[128 + 2 * t], bql1 = g_bf[128 + 2 * t + 1];
    float ex00 = __expf(C[16][0] + bql0);
    float ex01 = __expf(C[16][1] + bql1);
    float ex10 = __expf(C[16][2] + bql0);
    float ex11 = __expf(C[16][3] + bql1);

    float e0[8], e1[8];
#pragma unroll
    for (int tt = 0; tt < 4; tt++) {
        int sl = (lane & ~3) | tt;
        e0[2 * tt]     = __shfl_sync(0xffffffffu, ex00, sl);
        e0[2 * tt + 1] = __shfl_sync(0xffffffffu, ex01, sl);
        e1[2 * tt]     = __shfl_sync(0xffffffffu, ex10, sl);
        e1[2 * tt + 1] = __shfl_sync(0xffffffffu, ex11, sl);
    }
    if (v0) {
        g_w[(size_t)r0 * 8 + 2 * t]     = ex00;
        g_w[(size_t)r0 * 8 + 2 * t + 1] = ex01;
    }
    if (v1) {
        g_w[(size_t)r1 * 8 + 2 * t]     = ex10;
        g_w[(size_t)r1 * 8 + 2 * t + 1] = ex11;
    }
#pragma unroll
    for (int j = 0; j < 16; j++) {
        int c = j * 8 + 2 * t;
        int h = j >> 1;
        float2 bias = *(const float2*)&g_bf[c];
        if (v0) {
            float2 p = make_float2((C[j][0] + bias.x) * e0[h], (C[j][1] + bias.y) * e0[h]);
            *(__half2*)&g_P[(size_t)r0 * 128 + c] = __float22half2_rn(p);
        }
        if (v1) {
            float2 p = make_float2((C[j][2] + bias.x) * e1[h], (C[j][3] + bias.y) * e1[h]);
            *(__half2*)&g_P[(size_t)r1 * 128 + c] = __float22half2_rn(p);
        }
    }
}

// ---------------------------------------------------------------------------
// K2: warp-per-node gather. Coalesced csr + shfl broadcast; 4-edge groups
//     pair-summed in fp16 (HADD2), folded to fp32 once per group.
// ---------------------------------------------------------------------------
__global__ void __launch_bounds__(256) gather_kernel(float* __restrict__ out, int n)
{
    int warp = (blockIdx.x * blockDim.x + threadIdx.x) >> 5;
    int lane = threadIdx.x & 31;
    if (warp >= n) return;

    int beg = g_roff[warp];
    int deg = g_roff[warp + 1] - beg;
    int h   = lane >> 2;

    float4 acc = make_float4(0.f, 0.f, 0.f, 0.f);
    float den = 0.f;

    int i = 0;
    while (i < deg) {
        int cnt = min(32, deg - i);
        int sv = (lane < cnt) ? g_csr[beg + i + lane] : 0;
        int j = 0;
        for (; j + 4 <= cnt; j += 4) {
            int s0 = __shfl_sync(0xffffffffu, sv, j);
            int s1 = __shfl_sync(0xffffffffu, sv, j + 1);
            int s2 = __shfl_sync(0xffffffffu, sv, j + 2);
            int s3 = __shfl_sync(0xffffffffu, sv, j + 3);
            uint2 r0 = *(const uint2*)&g_P[(size_t)s0 * 128 + lane * 4];
            uint2 r1 = *(const uint2*)&g_P[(size_t)s1 * 128 + lane * 4];
            uint2 r2 = *(const uint2*)&g_P[(size_t)s2 * 128 + lane * 4];
            uint2 r3 = *(const uint2*)&g_P[(size_t)s3 * 128 + lane * 4];
            float w0 = g_w[(size_t)s0 * 8 + h];
            float w1 = g_w[(size_t)s1 * 8 + h];
            float w2 = g_w[(size_t)s2 * 8 + h];
            float w3 = g_w[(size_t)s3 * 8 + h];
            den += (w0 + w1) + (w2 + w3);
            __half2 sx = __hadd2(__hadd2(*(__half2*)&r0.x, *(__half2*)&r1.x),
                                 __hadd2(*(__half2*)&r2.x, *(__half2*)&r3.x));
            __half2 sy = __hadd2(__hadd2(*(__half2*)&r0.y, *(__half2*)&r1.y),
                                 __hadd2(*(__half2*)&r2.y, *(__half2*)&r3.y));
            float2 fx = __half22float2(sx);
            float2 fy = __half22float2(sy);
            acc.x += fx.x; acc.y += fx.y; acc.z += fy.x; acc.w += fy.y;
        }
        for (; j < cnt; j++) {
            int s = __shfl_sync(0xffffffffu, sv, j);
            uint2 r = *(const uint2*)&g_P[(size_t)s * 128 + lane * 4];
            den += g_w[(size_t)s * 8 + h];
            float2 a = __half22float2(*(__half2*)&r.x);
            float2 b = __half22float2(*(__half2*)&r.y);
            acc.x += a.x; acc.y += a.y; acc.z += b.x; acc.w += b.y;
        }
        i += cnt;
    }

    float inv = (den > 0.f) ? __frcp_rn(den) : 0.f;
    float4 o;
    o.x = fmaxf(acc.x * inv, 0.f);
    o.y = fmaxf(acc.y * inv, 0.f);
    o.z = fmaxf(acc.z * inv, 0.f);
    o.w = fmaxf(acc.w * inv, 0.f);
    *(float4*)&out[(size_t)warp * 128 + lane * 4] = o;
}

// ---------------------------------------------------------------------------
extern "C" void kernel_launch(void* const* d_in, const int* in_sizes, int n_in,
                              void* d_out, int out_size)
{
    const float* x   = (const float*)d_in[0];
    const float* Wq  = (const float*)d_in[1];
    const float* bq  = (const float*)d_in[2];
    // d_in[3] (Wk), d_in[4] (bk): unused -- kl cancels in the per-dst softmax
    const float* aw  = (const float*)d_in[5];
    const int*   src = (const int*)d_in[6];
    const int*   dst = (const int*)d_in[7];
    float* out = (float*)d_out;

    int n = in_sizes[0] / 128;
    int E = in_sizes[6];
    if (n > MAXN) n = MAXN;
    if (E > MAXE) E = MAXE;

    cudaFuncSetAttribute(fused_mid_kernel,
                         cudaFuncAttributeMaxDynamicSharedMemorySize, SMB_TOT);

    int eq         = (E + 3) / 4;
    int histBlocks = (eq + 255) / 256;      // also covers build_w's 17544 threads
    int gemmBlocks = (n + 127) / 128;       // 391
    int scatBlocks = (eq + 255) / 256;      // 586

    build_hist_kernel<<<histBlocks, 256>>>(Wq, bq, aw, dst, E);
    fused_mid_kernel<<<1 + gemmBlocks + scatBlocks, 256, SMB_TOT>>>(
        x, src, dst, n, E, gemmBlocks, scatBlocks);
    gather_kernel<<<((size_t)n * 32 + 255) / 256, 256>>>(out, n);
}

// round 14
// speedup vs baseline: 1.2460x; 1.2460x over previous
#include <cuda_runtime.h>
#include <cuda_bf16.h>
#include <cuda_fp16.h>
#include <cstdint>

// GATv2 with algebraic reductions:
//   attn[e,h] = exp(ql[src]) / sum_{s in N(dst)} exp(ql[s])   (kl cancels -> Wk/bk unused)
//   out[d] = relu( sum_{s in N(d)} P[s] / sum_{s in N(d)} w[s] ),
//   P = q * exp(ql) (fp16), w = exp(ql) (fp32), node-level (GEMM epilogue).
// 4 kernels: [build_w+hist] -> [scan(+re-zero cnt)] -> [gemm + scatter-tail] -> [gather].
// Invariant: g_cnt all-zero at entry (zero-init at load; scan re-zeroes each call).

#define MAXN 50000
#define MAXE 600000

__device__ __half         g_P   [MAXN * 128];   // q * exp(ql), fp16
__device__ float          g_w   [MAXN * 8];     // exp(ql)
__device__ __nv_bfloat16  g_Bhi [136 * 128];    // Wf^T hi  [c][k]
__device__ __nv_bfloat16  g_Blo [136 * 128];    // Wf^T lo
__device__ float          g_bf  [136];
__device__ int            g_cnt [MAXN + 4];     // ALWAYS zero between launches
__device__ int            g_roff[MAXN + 4];
__device__ int            g_cur [MAXN + 4];
__device__ int            g_csr [MAXE];

// ---------------------------------------------------------------------------
// K0: fused weight build (idx < 17544) + dst histogram (1 edge/thread: max MLP)
// ---------------------------------------------------------------------------
__global__ void build_hist_kernel(const float* __restrict__ Wq, const float* __restrict__ bq,
                                  const float* __restrict__ aw,
                                  const int* __restrict__ dst, int E)
{
    int idx = blockIdx.x * blockDim.x + threadIdx.x;
    if (idx < 128 * 136) {
        int r = idx / 136, c = idx % 136;   // r = k index, c = output col
        float v;
        if (c < 128) {
            v = Wq[r * 128 + c];
        } else {
            int h = c - 128;
            float s = 0.f;
#pragma unroll
            for (int d = 0; d < 16; d++) s += Wq[r * 128 + h * 16 + d] * aw[d * 8 + h];
            v = s;
        }
        __nv_bfloat16 hi = __float2bfloat16(v);
        __nv_bfloat16 lo = __float2bfloat16(v - __bfloat162float(hi));
        g_Bhi[c * 128 + r] = hi;
        g_Blo[c * 128 + r] = lo;
    } else if (idx < 128 * 136 + 136) {
        int c = idx - 128 * 136;
        float v;
        if (c < 128) {
            v = bq[c];
        } else {
            int h = c - 128;
            float s = 0.f;
#pragma unroll
            for (int d = 0; d < 16; d++) s += bq[h * 16 + d] * aw[d * 8 + h];
            v = s;
        }
        g_bf[c] = v;
    }
    if (idx < E) atomicAdd(&g_cnt[dst[idx]], 1);
}

// ---------------------------------------------------------------------------
// K1: vectorized exclusive scan -> g_roff + g_cur, re-zero g_cnt (invariant).
// ---------------------------------------------------------------------------
__global__ void scan_kernel(int n)
{
    __shared__ int sh[1024];
    int tid = threadIdx.x;
    int per = ((n + 1023) / 1024 + 3) & ~3;
    int beg = tid * per; if (beg > n) beg = n;
    int end = beg + per; if (end > n) end = n;

    int s = 0;
    int i = beg;
    for (; i + 4 <= end; i += 4) {
        int4 v = *(const int4*)&g_cnt[i];
        s += v.x + v.y + v.z + v.w;
    }
    for (; i < end; i++) s += g_cnt[i];
    sh[tid] = s;
    __syncthreads();
#pragma unroll
    for (int off = 1; off < 1024; off <<= 1) {
        int v = (tid >= off) ? sh[tid - off] : 0;
        __syncthreads();
        sh[tid] += v;
        __syncthreads();
    }
    int run = (tid > 0) ? sh[tid - 1] : 0;
    const int4 z4 = make_int4(0, 0, 0, 0);
    i = beg;
    for (; i + 4 <= end; i += 4) {
        int4 v = *(const int4*)&g_cnt[i];
        int4 p;
        p.x = run;
        p.y = p.x + v.x;
        p.z = p.y + v.y;
        p.w = p.z + v.z;
        run = p.w + v.w;
        *(int4*)&g_roff[i] = p;
        *(int4*)&g_cur[i]  = p;
        *(int4*)&g_cnt[i]  = z4;       // restore invariant
    }
    for (; i < end; i++) {
        g_roff[i] = run;
        g_cur[i]  = run;
        run += g_cnt[i];
        g_cnt[i] = 0;
    }
    if (tid == 1023) g_roff[n] = sh[1023];
}

// ---------------------------------------------------------------------------
// K2: mma.sync bf16 GEMM (128 rows x 136 cols per block) + scatter TAIL.
//     All 391 blocks are co-resident (3/SM x 148 SMs), so each block's
//     ~1.5K-edge scatter tail overlaps other blocks' MMA work.
// ---------------------------------------------------------------------------
#define B_STRIDE 272
#define SMB_HI   0
#define SMB_LO   (136 * B_STRIDE)
#define SMB_TOT  (2 * 136 * B_STRIDE)   // 73984 bytes

__device__ __forceinline__ void mma_bf16(float* c, const uint32_t* a,
                                         uint32_t b0, uint32_t b1) {
    asm volatile(
        "mma.sync.aligned.m16n8k16.row.col.f32.bf16.bf16.f32 "
        "{%0,%1,%2,%3}, {%4,%5,%6,%7}, {%8,%9}, {%0,%1,%2,%3};"
        : "+f"(c[0]), "+f"(c[1]), "+f"(c[2]), "+f"(c[3])
        : "r"(a[0]), "r"(a[1]), "r"(a[2]), "r"(a[3]), "r"(b0), "r"(b1));
}

__device__ __forceinline__ void cvt2(float2 f, uint32_t& hi, uint32_t& lo) {
    __nv_bfloat16 h0 = __float2bfloat16(f.x);
    __nv_bfloat16 h1 = __float2bfloat16(f.y);
    __nv_bfloat16 l0 = __float2bfloat16(f.x - __bfloat162float(h0));
    __nv_bfloat16 l1 = __float2bfloat16(f.y - __bfloat162float(h1));
    __nv_bfloat162 H(h0, h1), L(l0, l1);
    hi = *(uint32_t*)&H;
    lo = *(uint32_t*)&L;
}

__global__ void __launch_bounds__(256) gemm_scatter_kernel(
    const float* __restrict__ x, const int* __restrict__ src,
    const int* __restrict__ dst, int n, int E)
{
    extern __shared__ char smem[];
    int tid = threadIdx.x;
    int bid = blockIdx.x;

    // ---------------- gemm part ----------------
    char* bhi = smem + SMB_HI;
    char* blo = smem + SMB_LO;

    for (int idx = tid; idx < 136 * 16; idx += 256) {
        int row = idx >> 4, j = idx & 15;
        *(uint4*)(bhi + row * B_STRIDE + j * 16) = *(const uint4*)&g_Bhi[row * 128 + j * 8];
        *(uint4*)(blo + row * B_STRIDE + j * 16) = *(const uint4*)&g_Blo[row * 128 + j * 8];
    }
    __syncthreads();

    int w    = tid >> 5;
    int lane = tid & 31;
    int g    = lane >> 2;
    int t    = lane & 3;
    int rb   = bid * 128 + w * 16;
    int r0   = rb + g;
    int r1   = r0 + 8;
    int rc0  = (r0 < n) ? r0 : (n - 1);
    int rc1  = (r1 < n) ? r1 : (n - 1);
    const float* xr0 = &x[(size_t)rc0 * 128];
    const float* xr1 = &x[(size_t)rc1 * 128];

    float C[17][4];
#pragma unroll
    for (int j = 0; j < 17; j++)
#pragma unroll
        for (int q = 0; q < 4; q++) C[j][q] = 0.f;

    for (int k0 = 0; k0 < 128; k0 += 16) {
        float2 f00 = *(const float2*)&xr0[k0 + 2 * t];
        float2 f10 = *(const float2*)&xr1[k0 + 2 * t];
        float2 f01 = *(const float2*)&xr0[k0 + 2 * t + 8];
        float2 f11 = *(const float2*)&xr1[k0 + 2 * t + 8];
        uint32_t ah[4], al[4];
        cvt2(f00, ah[0], al[0]);
        cvt2(f10, ah[1], al[1]);
        cvt2(f01, ah[2], al[2]);
        cvt2(f11, ah[3], al[3]);

        const char* bh = bhi + k0 * 2 + t * 4;
        const char* bl = blo + k0 * 2 + t * 4;
#pragma unroll
        for (int j = 0; j < 17; j++) {
            int brow = (j * 8 + g) * B_STRIDE;
            uint32_t bh0 = *(const uint32_t*)(bh + brow);
            uint32_t bh1 = *(const uint32_t*)(bh + brow + 16);
            uint32_t bl0 = *(const uint32_t*)(bl + brow);
            uint32_t bl1 = *(const uint32_t*)(bl + brow + 16);
            mma_bf16(C[j], ah, bh0, bh1);
            mma_bf16(C[j], al, bh0, bh1);
            mma_bf16(C[j], ah, bl0, bl1);
        }
    }

    // epilogue: e = exp(ql + bias); quad-broadcast; write P (fp16) and w (fp32)
    bool v0 = (r0 < n), v1 = (r1 < n);
    float bql0 = g_bf[128 + 2 * t], bql1 = g_bf[128 + 2 * t + 1];
    float ex00 = __expf(C[16][0] + bql0);
    float ex01 = __expf(C[16][1] + bql1);
    float ex10 = __expf(C[16][2] + bql0);
    float ex11 = __expf(C[16][3] + bql1);

    float e0[8], e1[8];
#pragma unroll
    for (int tt = 0; tt < 4; tt++) {
        int sl = (lane & ~3) | tt;
        e0[2 * tt]     = __shfl_sync(0xffffffffu, ex00, sl);
        e0[2 * tt + 1] = __shfl_sync(0xffffffffu, ex01, sl);
        e1[2 * tt]     = __shfl_sync(0xffffffffu, ex10, sl);
        e1[2 * tt + 1] = __shfl_sync(0xffffffffu, ex11, sl);
    }
    if (v0) {
        g_w[(size_t)r0 * 8 + 2 * t]     = ex00;
        g_w[(size_t)r0 * 8 + 2 * t + 1] = ex01;
    }
    if (v1) {
        g_w[(size_t)r1 * 8 + 2 * t]     = ex10;
        g_w[(size_t)r1 * 8 + 2 * t + 1] = ex11;
    }
#pragma unroll
    for (int j = 0; j < 16; j++) {
        int c = j * 8 + 2 * t;
        int h = j >> 1;
        float2 bias = *(const float2*)&g_bf[c];
        if (v0) {
            float2 p = make_float2((C[j][0] + bias.x) * e0[h], (C[j][1] + bias.y) * e0[h]);
            *(__half2*)&g_P[(size_t)r0 * 128 + c] = __float22half2_rn(p);
        }
        if (v1) {
            float2 p = make_float2((C[j][2] + bias.x) * e1[h], (C[j][3] + bias.y) * e1[h]);
            *(__half2*)&g_P[(size_t)r1 * 128 + c] = __float22half2_rn(p);
        }
    }

    // ---------------- scatter tail (overlaps other blocks' MMA) ----------------
    int per  = (E + gridDim.x - 1) / gridDim.x;
    int ebeg = bid * per;
    int eend = ebeg + per; if (eend > E) eend = E;
    for (int e = ebeg + tid; e < eend; e += 256) {
        int pos = atomicAdd(&g_cur[dst[e]], 1);
        g_csr[pos] = src[e];
    }
}

// ---------------------------------------------------------------------------
// K3: warp-per-node gather. Coalesced csr + shfl broadcast; 4-edge groups
//     pair-summed in fp16 (HADD2), folded to fp32 once per group.
// ---------------------------------------------------------------------------
__global__ void __launch_bounds__(256) gather_kernel(float* __restrict__ out, int n)
{
    int warp = (blockIdx.x * blockDim.x + threadIdx.x) >> 5;
    int lane = threadIdx.x & 31;
    if (warp >= n) return;

    int beg = g_roff[warp];
    int deg = g_roff[warp + 1] - beg;
    int h   = lane >> 2;

    float4 acc = make_float4(0.f, 0.f, 0.f, 0.f);
    float den = 0.f;

    int i = 0;
    while (i < deg) {
        int cnt = min(32, deg - i);
        int sv = (lane < cnt) ? g_csr[beg + i + lane] : 0;
        int j = 0;
        for (; j + 4 <= cnt; j += 4) {
            int s0 = __shfl_sync(0xffffffffu, sv, j);
            int s1 = __shfl_sync(0xffffffffu, sv, j + 1);
            int s2 = __shfl_sync(0xffffffffu, sv, j + 2);
            int s3 = __shfl_sync(0xffffffffu, sv, j + 3);
            uint2 r0 = *(const uint2*)&g_P[(size_t)s0 * 128 + lane * 4];
            uint2 r1 = *(const uint2*)&g_P[(size_t)s1 * 128 + lane * 4];
            uint2 r2 = *(const uint2*)&g_P[(size_t)s2 * 128 + lane * 4];
            uint2 r3 = *(const uint2*)&g_P[(size_t)s3 * 128 + lane * 4];
            float w0 = g_w[(size_t)s0 * 8 + h];
            float w1 = g_w[(size_t)s1 * 8 + h];
            float w2 = g_w[(size_t)s2 * 8 + h];
            float w3 = g_w[(size_t)s3 * 8 + h];
            den += (w0 + w1) + (w2 + w3);
            __half2 sx = __hadd2(__hadd2(*(__half2*)&r0.x, *(__half2*)&r1.x),
                                 __hadd2(*(__half2*)&r2.x, *(__half2*)&r3.x));
            __half2 sy = __hadd2(__hadd2(*(__half2*)&r0.y, *(__half2*)&r1.y),
                                 __hadd2(*(__half2*)&r2.y, *(__half2*)&r3.y));
            float2 fx = __half22float2(sx);
            float2 fy = __half22float2(sy);
            acc.x += fx.x; acc.y += fx.y; acc.z += fy.x; acc.w += fy.y;
        }
        for (; j < cnt; j++) {
            int s = __shfl_sync(0xffffffffu, sv, j);
            uint2 r = *(const uint2*)&g_P[(size_t)s * 128 + lane * 4];
            den += g_w[(size_t)s * 8 + h];
            float2 a = __half22float2(*(__half2*)&r.x);
            float2 b = __half22float2(*(__half2*)&r.y);
            acc.x += a.x; acc.y += a.y; acc.z += b.x; acc.w += b.y;
        }
        i += cnt;
    }

    float inv = (den > 0.f) ? __frcp_rn(den) : 0.f;
    float4 o;
    o.x = fmaxf(acc.x * inv, 0.f);
    o.y = fmaxf(acc.y * inv, 0.f);
    o.z = fmaxf(acc.z * inv, 0.f);
    o.w = fmaxf(acc.w * inv, 0.f);
    *(float4*)&out[(size_t)warp * 128 + lane * 4] = o;
}

// ---------------------------------------------------------------------------
extern "C" void kernel_launch(void* const* d_in, const int* in_sizes, int n_in,
                              void* d_out, int out_size)
{
    const float* x   = (const float*)d_in[0];
    const float* Wq  = (const float*)d_in[1];
    const float* bq  = (const float*)d_in[2];
    // d_in[3] (Wk), d_in[4] (bk): unused -- kl cancels in the per-dst softmax
    const float* aw  = (const float*)d_in[5];
    const int*   src = (const int*)d_in[6];
    const int*   dst = (const int*)d_in[7];
    float* out = (float*)d_out;

    int n = in_sizes[0] / 128;
    int E = in_sizes[6];
    if (n > MAXN) n = MAXN;
    if (E > MAXE) E = MAXE;

    cudaFuncSetAttribute(gemm_scatter_kernel,
                         cudaFuncAttributeMaxDynamicSharedMemorySize, SMB_TOT);

    int gemmBlocks = (n + 127) / 128;       // 391

    build_hist_kernel<<<(E + 255) / 256, 256>>>(Wq, bq, aw, dst, E);
    scan_kernel<<<1, 1024>>>(n);
    gemm_scatter_kernel<<<gemmBlocks, 256, SMB_TOT>>>(x, src, dst, n, E);
    gather_kernel<<<((size_t)n * 32 + 255) / 256, 256>>>(out, n);
}

// round 15
// speedup vs baseline: 1.3908x; 1.1163x over previous
#include <cuda_runtime.h>
#include <cuda_bf16.h>
#include <cuda_fp16.h>
#include <cstdint>

// GATv2 with algebraic reductions:
//   attn[e,h] = exp(ql[src]) / sum_{s in N(dst)} exp(ql[s])   (kl cancels -> Wk/bk unused)
//   out[d] = relu( sum_{s in N(d)} P[s] / sum_{s in N(d)} w[s] ),
//   P = q * exp(ql) (fp16), w = exp(ql) (fp32), node-level (GEMM epilogue).
// 4 kernels: [build_w + hist(1e/t)] -> [scan(+re-zero)] -> [gemm|scatter split grid] -> [gather HADD2].
// Invariant: g_cnt all-zero at entry (zero-init at load; scan re-zeroes each call).

#define MAXN 50000
#define MAXE 600000

__device__ __half         g_P   [MAXN * 128];   // q * exp(ql), fp16
__device__ float          g_w   [MAXN * 8];     // exp(ql)
__device__ __nv_bfloat16  g_Bhi [136 * 128];    // Wf^T hi  [c][k]
__device__ __nv_bfloat16  g_Blo [136 * 128];    // Wf^T lo
__device__ float          g_bf  [136];
__device__ int            g_cnt [MAXN + 4];     // ALWAYS zero between launches
__device__ int            g_roff[MAXN + 4];
__device__ int            g_cur [MAXN + 4];
__device__ int            g_csr [MAXE];

// ---------------------------------------------------------------------------
// K0: fused weight build (idx < 17544) + dst histogram (1 edge/thread: max MLP)
// ---------------------------------------------------------------------------
__global__ void build_hist_kernel(const float* __restrict__ Wq, const float* __restrict__ bq,
                                  const float* __restrict__ aw,
                                  const int* __restrict__ dst, int E)
{
    int idx = blockIdx.x * blockDim.x + threadIdx.x;
    if (idx < 128 * 136) {
        int r = idx / 136, c = idx % 136;   // r = k index, c = output col
        float v;
        if (c < 128) {
            v = Wq[r * 128 + c];
        } else {
            int h = c - 128;
            float s = 0.f;
#pragma unroll
            for (int d = 0; d < 16; d++) s += Wq[r * 128 + h * 16 + d] * aw[d * 8 + h];
            v = s;
        }
        __nv_bfloat16 hi = __float2bfloat16(v);
        __nv_bfloat16 lo = __float2bfloat16(v - __bfloat162float(hi));
        g_Bhi[c * 128 + r] = hi;
        g_Blo[c * 128 + r] = lo;
    } else if (idx < 128 * 136 + 136) {
        int c = idx - 128 * 136;
        float v;
        if (c < 128) {
            v = bq[c];
        } else {
            int h = c - 128;
            float s = 0.f;
#pragma unroll
            for (int d = 0; d < 16; d++) s += bq[h * 16 + d] * aw[d * 8 + h];
            v = s;
        }
        g_bf[c] = v;
    }
    if (idx < E) atomicAdd(&g_cnt[dst[idx]], 1);
}

// ---------------------------------------------------------------------------
// K1: vectorized exclusive scan -> g_roff + g_cur, re-zero g_cnt (invariant).
// ---------------------------------------------------------------------------
__global__ void scan_kernel(int n)
{
    __shared__ int sh[1024];
    int tid = threadIdx.x;
    int per = ((n + 1023) / 1024 + 3) & ~3;
    int beg = tid * per; if (beg > n) beg = n;
    int end = beg + per; if (end > n) end = n;

    int s = 0;
    int i = beg;
    for (; i + 4 <= end; i += 4) {
        int4 v = *(const int4*)&g_cnt[i];
        s += v.x + v.y + v.z + v.w;
    }
    for (; i < end; i++) s += g_cnt[i];
    sh[tid] = s;
    __syncthreads();
#pragma unroll
    for (int off = 1; off < 1024; off <<= 1) {
        int v = (tid >= off) ? sh[tid - off] : 0;
        __syncthreads();
        sh[tid] += v;
        __syncthreads();
    }
    int run = (tid > 0) ? sh[tid - 1] : 0;
    const int4 z4 = make_int4(0, 0, 0, 0);
    i = beg;
    for (; i + 4 <= end; i += 4) {
        int4 v = *(const int4*)&g_cnt[i];
        int4 p;
        p.x = run;
        p.y = p.x + v.x;
        p.z = p.y + v.y;
        p.w = p.z + v.z;
        run = p.w + v.w;
        *(int4*)&g_roff[i] = p;
        *(int4*)&g_cur[i]  = p;
        *(int4*)&g_cnt[i]  = z4;       // restore invariant
    }
    for (; i < end; i++) {
        g_roff[i] = run;
        g_cur[i]  = run;
        run += g_cnt[i];
        g_cnt[i] = 0;
    }
    if (tid == 1023) g_roff[n] = sh[1023];
}

// ---------------------------------------------------------------------------
// K2: fused [gemm | scatter] by blockIdx (R11 champion structure).
//     Blocks [0, gemmBlocks): mma.sync bf16 GEMM (128 rows x 136 cols).
//     Blocks [gemmBlocks, ...): CSR scatter, 4 edges/thread (overlap wave).
// ---------------------------------------------------------------------------
#define B_STRIDE 272
#define SMB_HI   0
#define SMB_LO   (136 * B_STRIDE)
#define SMB_TOT  (2 * 136 * B_STRIDE)   // 73984 bytes

__device__ __forceinline__ void mma_bf16(float* c, const uint32_t* a,
                                         uint32_t b0, uint32_t b1) {
    asm volatile(
        "mma.sync.aligned.m16n8k16.row.col.f32.bf16.bf16.f32 "
        "{%0,%1,%2,%3}, {%4,%5,%6,%7}, {%8,%9}, {%0,%1,%2,%3};"
        : "+f"(c[0]), "+f"(c[1]), "+f"(c[2]), "+f"(c[3])
        : "r"(a[0]), "r"(a[1]), "r"(a[2]), "r"(a[3]), "r"(b0), "r"(b1));
}

__device__ __forceinline__ void cvt2(float2 f, uint32_t& hi, uint32_t& lo) {
    __nv_bfloat16 h0 = __float2bfloat16(f.x);
    __nv_bfloat16 h1 = __float2bfloat16(f.y);
    __nv_bfloat16 l0 = __float2bfloat16(f.x - __bfloat162float(h0));
    __nv_bfloat16 l1 = __float2bfloat16(f.y - __bfloat162float(h1));
    __nv_bfloat162 H(h0, h1), L(l0, l1);
    hi = *(uint32_t*)&H;
    lo = *(uint32_t*)&L;
}

__global__ void __launch_bounds__(256) gemm_scatter_kernel(
    const float* __restrict__ x, const int* __restrict__ src,
    const int* __restrict__ dst, int n, int E, int gemmBlocks)
{
    extern __shared__ char smem[];
    int tid = threadIdx.x;

    if ((int)blockIdx.x >= gemmBlocks) {
        // ---------------- scatter part ----------------
        int b = blockIdx.x - gemmBlocks;
        int t = b * 256 + tid;
        int T = (gridDim.x - gemmBlocks) * 256;
#pragma unroll
        for (int j = 0; j < 4; j++) {
            int e = t + j * T;
            if (e < E) {
                int pos = atomicAdd(&g_cur[dst[e]], 1);
                g_csr[pos] = src[e];
            }
        }
        return;
    }

    // ---------------- gemm part ----------------
    char* bhi = smem + SMB_HI;
    char* blo = smem + SMB_LO;

    for (int idx = tid; idx < 136 * 16; idx += 256) {
        int row = idx >> 4, j = idx & 15;
        *(uint4*)(bhi + row * B_STRIDE + j * 16) = *(const uint4*)&g_Bhi[row * 128 + j * 8];
        *(uint4*)(blo + row * B_STRIDE + j * 16) = *(const uint4*)&g_Blo[row * 128 + j * 8];
    }
    __syncthreads();

    int w    = tid >> 5;
    int lane = tid & 31;
    int g    = lane >> 2;
    int t    = lane & 3;
    int rb   = blockIdx.x * 128 + w * 16;
    int r0   = rb + g;
    int r1   = r0 + 8;
    int rc0  = (r0 < n) ? r0 : (n - 1);
    int rc1  = (r1 < n) ? r1 : (n - 1);
    const float* xr0 = &x[(size_t)rc0 * 128];
    const float* xr1 = &x[(size_t)rc1 * 128];

    float C[17][4];
#pragma unroll
    for (int j = 0; j < 17; j++)
#pragma unroll
        for (int q = 0; q < 4; q++) C[j][q] = 0.f;

    for (int k0 = 0; k0 < 128; k0 += 16) {
        float2 f00 = *(const float2*)&xr0[k0 + 2 * t];
        float2 f10 = *(const float2*)&xr1[k0 + 2 * t];
        float2 f01 = *(const float2*)&xr0[k0 + 2 * t + 8];
        float2 f11 = *(const float2*)&xr1[k0 + 2 * t + 8];
        uint32_t ah[4], al[4];
        cvt2(f00, ah[0], al[0]);
        cvt2(f10, ah[1], al[1]);
        cvt2(f01, ah[2], al[2]);
        cvt2(f11, ah[3], al[3]);

        const char* bh = bhi + k0 * 2 + t * 4;
        const char* bl = blo + k0 * 2 + t * 4;
#pragma unroll
        for (int j = 0; j < 17; j++) {
            int brow = (j * 8 + g) * B_STRIDE;
            uint32_t bh0 = *(const uint32_t*)(bh + brow);
            uint32_t bh1 = *(const uint32_t*)(bh + brow + 16);
            uint32_t bl0 = *(const uint32_t*)(bl + brow);
            uint32_t bl1 = *(const uint32_t*)(bl + brow + 16);
            mma_bf16(C[j], ah, bh0, bh1);
            mma_bf16(C[j], al, bh0, bh1);
            mma_bf16(C[j], ah, bl0, bl1);
        }
    }

    // epilogue: e = exp(ql + bias); quad-broadcast; write P (fp16) and w (fp32)
    bool v0 = (r0 < n), v1 = (r1 < n);
    float bql0 = g_bf[128 + 2 * t], bql1 = g_bf[128 + 2 * t + 1];
    float ex00 = __expf(C[16][0] + bql0);
    float ex01 = __expf(C[16][1] + bql1);
    float ex10 = __expf(C[16][2] + bql0);
    float ex11 = __expf(C[16][3] + bql1);

    float e0[8], e1[8];
#pragma unroll
    for (int tt = 0; tt < 4; tt++) {
        int sl = (lane & ~3) | tt;
        e0[2 * tt]     = __shfl_sync(0xffffffffu, ex00, sl);
        e0[2 * tt + 1] = __shfl_sync(0xffffffffu, ex01, sl);
        e1[2 * tt]     = __shfl_sync(0xffffffffu, ex10, sl);
        e1[2 * tt + 1] = __shfl_sync(0xffffffffu, ex11, sl);
    }
    if (v0) {
        g_w[(size_t)r0 * 8 + 2 * t]     = ex00;
        g_w[(size_t)r0 * 8 + 2 * t + 1] = ex01;
    }
    if (v1) {
        g_w[(size_t)r1 * 8 + 2 * t]     = ex10;
        g_w[(size_t)r1 * 8 + 2 * t + 1] = ex11;
    }
#pragma unroll
    for (int j = 0; j < 16; j++) {
        int c = j * 8 + 2 * t;
        int h = j >> 1;
        float2 bias = *(const float2*)&g_bf[c];
        if (v0) {
            float2 p = make_float2((C[j][0] + bias.x) * e0[h], (C[j][1] + bias.y) * e0[h]);
            *(__half2*)&g_P[(size_t)r0 * 128 + c] = __float22half2_rn(p);
        }
        if (v1) {
            float2 p = make_float2((C[j][2] + bias.x) * e1[h], (C[j][3] + bias.y) * e1[h]);
            *(__half2*)&g_P[(size_t)r1 * 128 + c] = __float22half2_rn(p);
        }
    }
}

// ---------------------------------------------------------------------------
// K3: warp-per-node gather. Coalesced csr + shfl broadcast; 4-edge groups
//     pair-summed in fp16 (HADD2), folded to fp32 once per group.
// ---------------------------------------------------------------------------
__global__ void __launch_bounds__(256) gather_kernel(float* __restrict__ out, int n)
{
    int warp = (blockIdx.x * blockDim.x + threadIdx.x) >> 5;
    int lane = threadIdx.x & 31;
    if (warp >= n) return;

    int beg = g_roff[warp];
    int deg = g_roff[warp + 1] - beg;
    int h   = lane >> 2;

    float4 acc = make_float4(0.f, 0.f, 0.f, 0.f);
    float den = 0.f;

    int i = 0;
    while (i < deg) {
        int cnt = min(32, deg - i);
        int sv = (lane < cnt) ? g_csr[beg + i + lane] : 0;
        int j = 0;
        for (; j + 4 <= cnt; j += 4) {
            int s0 = __shfl_sync(0xffffffffu, sv, j);
            int s1 = __shfl_sync(0xffffffffu, sv, j + 1);
            int s2 = __shfl_sync(0xffffffffu, sv, j + 2);
            int s3 = __shfl_sync(0xffffffffu, sv, j + 3);
            uint2 r0 = *(const uint2*)&g_P[(size_t)s0 * 128 + lane * 4];
            uint2 r1 = *(const uint2*)&g_P[(size_t)s1 * 128 + lane * 4];
            uint2 r2 = *(const uint2*)&g_P[(size_t)s2 * 128 + lane * 4];
            uint2 r3 = *(const uint2*)&g_P[(size_t)s3 * 128 + lane * 4];
            float w0 = g_w[(size_t)s0 * 8 + h];
            float w1 = g_w[(size_t)s1 * 8 + h];
            float w2 = g_w[(size_t)s2 * 8 + h];
            float w3 = g_w[(size_t)s3 * 8 + h];
            den += (w0 + w1) + (w2 + w3);
            __half2 sx = __hadd2(__hadd2(*(__half2*)&r0.x, *(__half2*)&r1.x),
                                 __hadd2(*(__half2*)&r2.x, *(__half2*)&r3.x));
            __half2 sy = __hadd2(__hadd2(*(__half2*)&r0.y, *(__half2*)&r1.y),
                                 __hadd2(*(__half2*)&r2.y, *(__half2*)&r3.y));
            float2 fx = __half22float2(sx);
            float2 fy = __half22float2(sy);
            acc.x += fx.x; acc.y += fx.y; acc.z += fy.x; acc.w += fy.y;
        }
        for (; j < cnt; j++) {
            int s = __shfl_sync(0xffffffffu, sv, j);
            uint2 r = *(const uint2*)&g_P[(size_t)s * 128 + lane * 4];
            den += g_w[(size_t)s * 8 + h];
            float2 a = __half22float2(*(__half2*)&r.x);
            float2 b = __half22float2(*(__half2*)&r.y);
            acc.x += a.x; acc.y += a.y; acc.z += b.x; acc.w += b.y;
        }
        i += cnt;
    }

    float inv = (den > 0.f) ? __frcp_rn(den) : 0.f;
    float4 o;
    o.x = fmaxf(acc.x * inv, 0.f);
    o.y = fmaxf(acc.y * inv, 0.f);
    o.z = fmaxf(acc.z * inv, 0.f);
    o.w = fmaxf(acc.w * inv, 0.f);
    *(float4*)&out[(size_t)warp * 128 + lane * 4] = o;
}

// ---------------------------------------------------------------------------
extern "C" void kernel_launch(void* const* d_in, const int* in_sizes, int n_in,
                              void* d_out, int out_size)
{
    const float* x   = (const float*)d_in[0];
    const float* Wq  = (const float*)d_in[1];
    const float* bq  = (const float*)d_in[2];
    // d_in[3] (Wk), d_in[4] (bk): unused -- kl cancels in the per-dst softmax
    const float* aw  = (const float*)d_in[5];
    const int*   src = (const int*)d_in[6];
    const int*   dst = (const int*)d_in[7];
    float* out = (float*)d_out;

    int n = in_sizes[0] / 128;
    int E = in_sizes[6];
    if (n > MAXN) n = MAXN;
    if (E > MAXE) E = MAXE;

    cudaFuncSetAttribute(gemm_scatter_kernel,
                         cudaFuncAttributeMaxDynamicSharedMemorySize, SMB_TOT);

    int eq         = (E + 3) / 4;
    int gemmBlocks = (n + 127) / 128;       // 391
    int scatBlocks = (eq + 255) / 256;      // 586

    build_hist_kernel<<<(E + 255) / 256, 256>>>(Wq, bq, aw, dst, E);
    scan_kernel<<<1, 1024>>>(n);
    gemm_scatter_kernel<<<gemmBlocks + scatBlocks, 256, SMB_TOT>>>(
        x, src, dst, n, E, gemmBlocks);
    gather_kernel<<<((size_t)n * 32 + 255) / 256, 256>>>(out, n);
}